// round 14
// baseline (speedup 1.0000x reference)
#include <cuda_runtime.h>
#include <cstdint>
#include <math.h>

// Problem constants
#define BB   4
#define CC   64
#define C2C  32
#define HH   48
#define WWD  48
#define HWN  2304          // 48*48
#define LT   7470          // total key positions across 5 scales
#define LPD  7488          // L padded to multiple of 64
#define NKC  13            // split-K chunks in gemm2
#define KCH  576           // LPD / NKC = 18 * 32

__constant__ int   c_off[5]   = {0, 2304, 4153, 5597, 6686};
__constant__ int   c_size[5]  = {48, 43, 38, 33, 28};
__constant__ float c_scale[5] = {1.0f, 0.9f, 0.8f, 0.7f, 0.6f};

// Scratch (static device globals; no allocation)
__device__ float g_mb  [(size_t)BB * C2C * HWN];
__device__ float g_ref [(size_t)BB * CC  * LT];
__device__ float g_fm  [(size_t)BB * C2C * LT];
__device__ float g_fa  [(size_t)BB * CC  * LPD];   // stride LPD (16B-aligned rows)
__device__ float g_E   [(size_t)BB * LT];
__device__ float g_inv [(size_t)BB * LT];          // 10 / max(norm, esc)
__device__ int   g_meta[LT];
__device__ float g_D   [(size_t)BB * HWN * LPD];   // D = mb^T * fm
__device__ float g_A   [(size_t)BB * HWN * LPD];   // attention weights
__device__ float g_part[(size_t)BB * NKC * HWN * CC]; // split-K partials

__device__ __forceinline__ float prelu(float v, float a) {
    return v >= 0.f ? v : a * v;
}

// FMA-pipe exp (valid for x <= 0): 2^z split + degree-7 poly, rel err ~5e-9.
__device__ __forceinline__ float fexp(float x) {
    float z = x * 1.4426950408889634f;
    z = fmaxf(z, -126.f);
    float r = rintf(z);
    float f = z - r;
    float p =           1.52527338e-5f;
    p = fmaf(p, f, 1.54035304e-4f);
    p = fmaf(p, f, 1.33335581e-3f);
    p = fmaf(p, f, 9.61812911e-3f);
    p = fmaf(p, f, 5.55041087e-2f);
    p = fmaf(p, f, 2.40226507e-1f);
    p = fmaf(p, f, 6.93147181e-1f);
    p = fmaf(p, f, 1.0f);
    int i = (int)r;
    return __int_as_float(__float_as_int(p) + (i << 23));
}

__device__ __forceinline__ uint32_t to_tf32(float x) {
    uint32_t r;
    asm("cvt.rn.tf32.f32 %0, %1;" : "=r"(r) : "f"(x));
    return r;
}

__device__ __forceinline__ float cubicw(float x) {   // torch bicubic, A=-0.75
    x = fabsf(x);
    if (x <= 1.f)  return (1.25f * x - 2.25f) * x * x + 1.f;
    if (x <  2.f)  return ((-0.75f * x + 3.75f) * x - 6.f) * x + 3.f;
    return 0.f;
}

__device__ __forceinline__ int find_scale(int l) {
    if (l < c_off[1]) return 0;
    if (l < c_off[2]) return 1;
    if (l < c_off[3]) return 2;
    if (l < c_off[4]) return 3;
    return 4;
}

__device__ __forceinline__ float warp_sum(float v) {
    #pragma unroll
    for (int o = 16; o > 0; o >>= 1) v += __shfl_down_sync(0xffffffffu, v, o);
    return v;
}
__device__ __forceinline__ float warp_max(float v) {
    #pragma unroll
    for (int o = 16; o > 0; o >>= 1) v = fmaxf(v, __shfl_down_sync(0xffffffffu, v, o));
    return v;
}

// ---------------------------------------------------------------------------
// 0. Per-l metadata: scale width n + scale-grid boundary validity bits
// ---------------------------------------------------------------------------
__global__ void k_meta() {
    int l = blockIdx.x * 256 + threadIdx.x;
    if (l >= LT) return;
    int s  = find_scale(l);
    int ll = l - c_off[s];
    int n  = c_size[s];
    int hl = ll / n, wl = ll - hl * n;
    int m = n;
    if (hl > 0)     m |= 1 << 8;
    if (hl < n - 1) m |= 1 << 9;
    if (wl > 0)     m |= 1 << 10;
    if (wl < n - 1) m |= 1 << 11;
    g_meta[l] = m;
}

// ---------------------------------------------------------------------------
// 1. match_base = prelu(w_mb @ x + b_mb) -> [B, 32, 2304]
// ---------------------------------------------------------------------------
__global__ void k_mb(const float* __restrict__ x, const float* __restrict__ w,
                     const float* __restrict__ b, const float* __restrict__ a) {
    int idx = blockIdx.x * blockDim.x + threadIdx.x;
    if (idx >= BB * C2C * HWN) return;
    int p  = idx % HWN;
    int t  = idx / HWN;
    int c2 = t % C2C;
    int bb = t / C2C;
    const float* xb = x + (size_t)bb * CC * HWN;
    float s = b[c2];
    #pragma unroll 8
    for (int c = 0; c < CC; c++) s = fmaf(w[c2 * CC + c], xb[(size_t)c * HWN + p], s);
    g_mb[idx] = prelu(s, a[0]);
}

// ---------------------------------------------------------------------------
// 2. Pyramid ref images (bicubic downsample; scale 0 = identity copy)
// ---------------------------------------------------------------------------
__global__ void k_ref(const float* __restrict__ x) {
    int idx = blockIdx.x * blockDim.x + threadIdx.x;
    if (idx >= BB * CC * LT) return;
    int l  = idx % LT;
    int t  = idx / LT;
    int c  = t % CC;
    int bb = t / CC;
    int s  = find_scale(l);
    int ll = l - c_off[s];
    const float* xb = x + ((size_t)bb * CC + c) * HWN;
    float out;
    if (s == 0) {
        out = xb[ll];
    } else {
        int n  = c_size[s];
        int oh = ll / n, ow = ll % n;
        float sc   = c_scale[s];
        float srcy = (oh + 0.5f) / sc - 0.5f;
        float srcx = (ow + 0.5f) / sc - 0.5f;
        int   fy = (int)floorf(srcy);
        int   fx = (int)floorf(srcx);
        float fry = srcy - fy, frx = srcx - fx;
        float wy[4], wx[4];
        #pragma unroll
        for (int k = 0; k < 4; k++) {
            wy[k] = cubicw((float)(k - 1) - fry);
            wx[k] = cubicw((float)(k - 1) - frx);
        }
        out = 0.f;
        #pragma unroll
        for (int ky = 0; ky < 4; ky++) {
            int iy = min(max(fy + ky - 1, 0), HH - 1);
            float acc = 0.f;
            #pragma unroll
            for (int kx = 0; kx < 4; kx++) {
                int ix = min(max(fx + kx - 1, 0), WWD - 1);
                acc = fmaf(wx[kx], xb[iy * WWD + ix], acc);
            }
            out = fmaf(wy[ky], acc, out);
        }
    }
    g_ref[idx] = out;
}

// ---------------------------------------------------------------------------
// 3. Both 1x1 convs over the pyramid in one pass (smem-tiled)
// ---------------------------------------------------------------------------
#define CT 64
__global__ void k_convs(const float* __restrict__ w_m, const float* __restrict__ b_m,
                        const float* __restrict__ a_m,
                        const float* __restrict__ w_a, const float* __restrict__ b_a,
                        const float* __restrict__ a_a) {
    __shared__ float sRef[CC][CT];
    __shared__ float sW[96][CC];
    int bb = blockIdx.y;
    int l0 = blockIdx.x * CT;
    int tid = threadIdx.x;
    for (int e = tid; e < 96 * CC; e += 256) {
        int co = e / CC, c = e % CC;
        sW[co][c] = (co < C2C) ? w_m[co * CC + c] : w_a[(co - C2C) * CC + c];
    }
    for (int e = tid; e < CC * CT; e += 256) {
        int c = e / CT, j = e % CT;
        sRef[c][j] = (l0 + j < LT) ? g_ref[((size_t)bb * CC + c) * LT + l0 + j] : 0.f;
    }
    __syncthreads();
    float am = a_m[0], aa = a_a[0];
    for (int o = tid; o < 96 * CT; o += 256) {
        int co = o / CT, j = o % CT;
        if (l0 + j >= LT) continue;
        float s = (co < C2C) ? b_m[co] : b_a[co - C2C];
        #pragma unroll 16
        for (int c = 0; c < CC; c++) s = fmaf(sW[co][c], sRef[c][j], s);
        if (co < C2C)
            g_fm[((size_t)bb * C2C + co) * LT + l0 + j] = prelu(s, am);
        else
            g_fa[((size_t)bb * CC + (co - C2C)) * LPD + l0 + j] = prelu(s, aa);
    }
}

// ---------------------------------------------------------------------------
// 4. E[b,l] = sum_c2 fm^2 ; inv10 = 10 / max(sqrt(blur9(E)), esc)
// ---------------------------------------------------------------------------
__global__ void k_E() {
    int idx = blockIdx.x * 256 + threadIdx.x;
    if (idx >= BB * LT) return;
    int l = idx % LT, bb = idx / LT;
    float s = 0.f;
    #pragma unroll 8
    for (int c2 = 0; c2 < C2C; c2++) {
        float v = g_fm[((size_t)bb * C2C + c2) * LT + l];
        s = fmaf(v, v, s);
    }
    g_E[idx] = s;
}

__global__ void k_inv(const float* __restrict__ esc) {
    int idx = blockIdx.x * 256 + threadIdx.x;
    if (idx >= BB * LT) return;
    int l = idx % LT, bb = idx / LT;
    int m = g_meta[l];
    int n = m & 255;
    int my0 = (m >> 8) & 1, my2 = (m >> 9) & 1;
    int mx0 = (m >> 10) & 1, mx2 = (m >> 11) & 1;
    const float* E = g_E + (size_t)bb * LT;
    float s = 0.f;
    #pragma unroll
    for (int dy = 0; dy < 3; dy++) {
        int yok = (dy == 0) ? my0 : (dy == 2) ? my2 : 1;
        if (!yok) continue;
        #pragma unroll
        for (int dx = 0; dx < 3; dx++) {
            int xok = (dx == 0) ? mx0 : (dx == 2) ? mx2 : 1;
            if (!xok) continue;
            s += E[l + (dy - 1) * n + (dx - 1)];
        }
    }
    g_inv[idx] = 10.f / fmaxf(sqrtf(s), esc[0]);
}

// ---------------------------------------------------------------------------
// 5. D = mb^T * fm : [2304, LPD], K=32  (pad cols -> 0), float4 fragments
// ---------------------------------------------------------------------------
__global__ void __launch_bounds__(256) k_D() {
    int bb = blockIdx.z;
    int m0 = blockIdx.y * 64, n0 = blockIdx.x * 64;
    __shared__ __align__(16) float As[C2C][68];
    __shared__ __align__(16) float Bs[C2C][68];
    int tid = threadIdx.y * 16 + threadIdx.x;
    #pragma unroll
    for (int t = 0; t < 8; t++) {
        int e = tid + t * 256;
        int k = e >> 6, col = e & 63;
        As[k][col] = g_mb[((size_t)bb * C2C + k) * HWN + m0 + col];
        Bs[k][col] = (n0 + col < LT) ? g_fm[((size_t)bb * C2C + k) * LT + n0 + col] : 0.f;
    }
    __syncthreads();
    float acc[4][4] = {};
    #pragma unroll
    for (int kk = 0; kk < C2C; kk++) {
        float4 a4 = *(const float4*)&As[kk][threadIdx.y * 4];
        float4 b4 = *(const float4*)&Bs[kk][threadIdx.x * 4];
        float av[4] = {a4.x, a4.y, a4.z, a4.w};
        float bv[4] = {b4.x, b4.y, b4.z, b4.w};
        #pragma unroll
        for (int i = 0; i < 4; i++)
            #pragma unroll
            for (int j = 0; j < 4; j++) acc[i][j] = fmaf(av[i], bv[j], acc[i][j]);
    }
    float* Dp = g_D + (size_t)bb * HWN * LPD;
    #pragma unroll
    for (int i = 0; i < 4; i++) {
        float4 v = make_float4(acc[i][0], acc[i][1], acc[i][2], acc[i][3]);
        *(float4*)&Dp[(size_t)(m0 + threadIdx.y * 4 + i) * LPD + n0 + threadIdx.x * 4] = v;
    }
}

// ---------------------------------------------------------------------------
// 6. Fused softmax (two-pass over fp32 smem): S = inv[l]*blur9(D) -> softmax
//    -> A row (fp32).  1 block per (b,p). float4 passes 2/3.
// ---------------------------------------------------------------------------
#define LT4 7472    // LT rounded up to multiple of 4
__global__ void __launch_bounds__(256) k_sm() {
    int bp = blockIdx.x;
    int p  = bp % HWN;
    int bb = bp / HWN;
    int h = p / WWD, w = p % WWD;
    int hy0 = (h > 0), hy2 = (h < HH - 1);
    int wx0 = (w > 0), wx2 = (w < WWD - 1);
    const float* D = g_D + (size_t)bb * HWN * LPD + (size_t)p * LPD;
    float* A = g_A + (size_t)bb * HWN * LPD + (size_t)p * LPD;
    const float* inv = g_inv + (size_t)bb * LT;

    __shared__ __align__(16) float buf[LT4];
    __shared__ float red[8];
    int tid = threadIdx.x;
    float mx = -1e30f;
    for (int l = tid; l < LT; l += 256) {
        int m = g_meta[l];
        int n = m & 255;
        float acc = 0.f;
        #pragma unroll
        for (int dy = 0; dy < 3; dy++) {
            int yok = (dy == 0) ? (hy0 & ((m >> 8) & 1))
                    : (dy == 2) ? (hy2 & ((m >> 9) & 1)) : 1;
            if (!yok) continue;
            const float* Drow = D + (dy - 1) * WWD * LPD + (dy - 1) * n;
            #pragma unroll
            for (int dx = 0; dx < 3; dx++) {
                int xok = (dx == 0) ? (wx0 & ((m >> 10) & 1))
                        : (dx == 2) ? (wx2 & ((m >> 11) & 1)) : 1;
                if (!xok) continue;
                acc += Drow[(dx - 1) * LPD + l + (dx - 1)];
            }
        }
        float v = acc * inv[l];
        buf[l] = v;
        mx = fmaxf(mx, v);
    }
    if (tid < LT4 - LT) buf[LT + tid] = -1e30f;   // sentinel pad (exp -> ~0)
    mx = warp_max(mx);
    if ((tid & 31) == 0) red[tid >> 5] = mx;
    __syncthreads();
    if (tid < 8) {
        float v = red[tid];
        #pragma unroll
        for (int o = 4; o > 0; o >>= 1) v = fmaxf(v, __shfl_down_sync(0xffu, v, o));
        if (tid == 0) red[0] = v;
    }
    __syncthreads();
    mx = red[0];
    __syncthreads();
    float sum = 0.f;
    for (int l4 = tid * 4; l4 < LT4; l4 += 1024) {
        float4 v = *(float4*)&buf[l4];
        v.x = fexp(v.x - mx);
        v.y = fexp(v.y - mx);
        v.z = fexp(v.z - mx);
        v.w = fexp(v.w - mx);
        *(float4*)&buf[l4] = v;
        sum += (v.x + v.y) + (v.z + v.w);
    }
    sum = warp_sum(sum);
    if ((tid & 31) == 0) red[tid >> 5] = sum;
    __syncthreads();
    if (tid < 8) {
        float v = red[tid];
        #pragma unroll
        for (int o = 4; o > 0; o >>= 1) v += __shfl_down_sync(0xffu, v, o);
        if (tid == 0) red[0] = v;
    }
    __syncthreads();
    float is = 1.f / red[0];
    for (int l4 = tid * 4; l4 < LT4; l4 += 1024) {
        float4 v = *(float4*)&buf[l4];
        v.x *= is; v.y *= is; v.z *= is; v.w *= is;
        *(float4*)&A[l4] = v;
    }
}

// ---------------------------------------------------------------------------
// 7. Split-K partial GEMM with fused blur9(A) tile build, tf32 mma.sync:
//    grid (72 m-tiles, 13 k-chunks, B); block 128 = 4 warps; 32x64 tile, TK=32
//    warp w: m-half (w&1)*16, n-half (w>>1)*32 (4 n-subtiles of 8).
// ---------------------------------------------------------------------------
#define TKM 32
__global__ void __launch_bounds__(128) k_gemm2p() {
    int bb = blockIdx.z;
    int kc = blockIdx.y;
    int m0 = blockIdx.x * 32;
    __shared__ __align__(16) uint32_t As[32][36];   // [m][k] tf32
    __shared__ __align__(16) uint32_t Bs[64][36];   // [c][k] tf32
    int tid  = threadIdx.x;
    int wid  = tid >> 5;
    int lane = tid & 31;
    int mh = (wid & 1) * 16;
    int nh = (wid >> 1) * 32;
    const float* Ab = g_A + (size_t)bb * HWN * LPD;
    const float* fa = g_fa + (size_t)bb * CC * LPD;
    float acc[4][4] = {};
    int kend = kc * KCH + KCH;
    for (int k0 = kc * KCH; k0 < kend; k0 += TKM) {
        // ---- blurred A tile: 32 m x 32 k, tf32; 8 elems/thread ----
        #pragma unroll
        for (int t = 0; t < 8; t++) {
            int e = tid + t * 128;
            int r = e >> 5, kk = e & 31;
            int l = k0 + kk;
            float v = 0.f;
            if (l < LT) {
                int p = m0 + r;
                int h = p / WWD, w = p % WWD;
                int hy0 = (h > 0), hy2 = (h < HH - 1);
                int wx0 = (w > 0), wx2 = (w < WWD - 1);
                int m = g_meta[l];
                int n = m & 255;
                const float* Arow = Ab + (size_t)p * LPD + l;
                #pragma unroll
                for (int dy = 0; dy < 3; dy++) {
                    int yok = (dy == 0) ? (hy0 & ((m >> 8) & 1))
                            : (dy == 2) ? (hy2 & ((m >> 9) & 1)) : 1;
                    if (!yok) continue;
                    const float* Ar2 = Arow + (dy - 1) * (WWD * LPD) + (dy - 1) * n;
                    #pragma unroll
                    for (int dx = 0; dx < 3; dx++) {
                        int xok = (dx == 0) ? (wx0 & ((m >> 10) & 1))
                                : (dx == 2) ? (wx2 & ((m >> 11) & 1)) : 1;
                        if (!xok) continue;
                        v += Ar2[(dx - 1) * LPD + (dx - 1)];
                    }
                }
            }
            As[r][kk] = to_tf32(v);
        }
        // ---- fa tile: 64 c x 32 k, tf32; float4 loads, 4/thread ----
        #pragma unroll
        for (int t = 0; t < 4; t++) {
            int e = tid + t * 128;          // [0, 512)
            int c = e >> 3;                 // 0..63
            int q = e & 7;                  // 0..7 (quad within 32 k)
            int l = k0 + q * 4;
            float4 v = *(const float4*)&fa[(size_t)c * LPD + l];
            uint4 tv;
            tv.x = to_tf32((l + 0 < LT) ? v.x : 0.f);
            tv.y = to_tf32((l + 1 < LT) ? v.y : 0.f);
            tv.z = to_tf32((l + 2 < LT) ? v.z : 0.f);
            tv.w = to_tf32((l + 3 < LT) ? v.w : 0.f);
            *(uint4*)&Bs[c][q * 4] = tv;
        }
        __syncthreads();
        // ---- mma main: 4 k-steps of 8 ----
        #pragma unroll
        for (int ks = 0; ks < 4; ks++) {
            int kb = ks * 8;
            int lr = lane >> 2;     // 0..7
            int lc = lane & 3;      // 0..3
            uint32_t a0 = As[mh + lr][kb + lc];
            uint32_t a1 = As[mh + lr + 8][kb + lc];
            uint32_t a2 = As[mh + lr][kb + lc + 4];
            uint32_t a3 = As[mh + lr + 8][kb + lc + 4];
            #pragma unroll
            for (int s = 0; s < 4; s++) {
                uint32_t b0 = Bs[nh + s * 8 + lr][kb + lc];
                uint32_t b1 = Bs[nh + s * 8 + lr][kb + lc + 4];
                asm volatile(
                    "mma.sync.aligned.m16n8k8.row.col.f32.tf32.tf32.f32 "
                    "{%0,%1,%2,%3}, {%4,%5,%6,%7}, {%8,%9}, {%0,%1,%2,%3};"
                    : "+f"(acc[s][0]), "+f"(acc[s][1]), "+f"(acc[s][2]), "+f"(acc[s][3])
                    : "r"(a0), "r"(a1), "r"(a2), "r"(a3), "r"(b0), "r"(b1));
            }
        }
        __syncthreads();
    }
    // ---- epilogue: D fragment scatter (float2 stores, cols 2j,2j+1) ----
    int lr = lane >> 2, lc = lane & 3;
    int p_lo = m0 + mh + lr;
    int ccol = nh + 2 * lc;
    size_t base = ((size_t)bb * NKC + kc) * HWN;
    #pragma unroll
    for (int s = 0; s < 4; s++) {
        int c = ccol + s * 8;
        *(float2*)&g_part[(base + p_lo) * CC + c]     = make_float2(acc[s][0], acc[s][1]);
        *(float2*)&g_part[(base + p_lo + 8) * CC + c] = make_float2(acc[s][2], acc[s][3]);
    }
}

// ---------------------------------------------------------------------------
// 8. Reduce split-K partials + residual: y[b,c,p] = x + 0.25 * sum_kc part
// ---------------------------------------------------------------------------
__global__ void k_out(const float* __restrict__ x, float* __restrict__ out) {
    int idx = blockIdx.x * 256 + threadIdx.x;
    if (idx >= BB * HWN * CC) return;
    int c  = idx % CC;
    int t  = idx / CC;
    int p  = t % HWN;
    int bb = t / HWN;
    float s = 0.f;
    #pragma unroll
    for (int kc = 0; kc < NKC; kc++)
        s += g_part[(((size_t)bb * NKC + kc) * HWN + p) * CC + c];
    size_t o = ((size_t)bb * CC + c) * HWN + p;
    out[o] = x[o] + 0.25f * s;
}

// ---------------------------------------------------------------------------
extern "C" void kernel_launch(void* const* d_in, const int* in_sizes, int n_in,
                              void* d_out, int out_size) {
    const float* x    = (const float*)d_in[0];
    const float* w_mb = (const float*)d_in[1];
    const float* b_mb = (const float*)d_in[2];
    const float* a_mb = (const float*)d_in[3];
    const float* w_m  = (const float*)d_in[4];
    const float* b_m  = (const float*)d_in[5];
    const float* a_m  = (const float*)d_in[6];
    const float* w_a  = (const float*)d_in[7];
    const float* b_a  = (const float*)d_in[8];
    const float* a_a  = (const float*)d_in[9];
    const float* esc  = (const float*)d_in[10];
    float* out = (float*)d_out;

    k_meta<<<(LT + 255) / 256, 256>>>();

    int n = BB * C2C * HWN;
    k_mb<<<(n + 255) / 256, 256>>>(x, w_mb, b_mb, a_mb);

    n = BB * CC * LT;
    k_ref<<<(n + 255) / 256, 256>>>(x);

    {
        dim3 grid((LT + CT - 1) / CT, BB);
        k_convs<<<grid, 256>>>(w_m, b_m, a_m, w_a, b_a, a_a);
    }

    n = BB * LT;
    k_E<<<(n + 255) / 256, 256>>>();
    k_inv<<<(n + 255) / 256, 256>>>(esc);

    {
        dim3 grid(LPD / 64, HWN / 64, BB), block(16, 16);
        k_D<<<grid, block>>>();
    }

    k_sm<<<BB * HWN, 256>>>();

    {
        dim3 grid(HWN / 32, NKC, BB);
        k_gemm2p<<<grid, 128>>>();
    }

    n = BB * HWN * CC;
    k_out<<<(n + 255) / 256, 256>>>(x, out);
}

// round 16
// speedup vs baseline: 1.0774x; 1.0774x over previous
#include <cuda_runtime.h>
#include <cstdint>
#include <math.h>

// Problem constants
#define BB   4
#define CC   64
#define C2C  32
#define HH   48
#define WWD  48
#define HWN  2304          // 48*48
#define LT   7470          // total key positions across 5 scales
#define LPD  7488          // L padded to multiple of 64
#define NKC  13            // split-K chunks in gemm2
#define KCH  576           // LPD / NKC = 24 * 24

__constant__ int   c_off[5]   = {0, 2304, 4153, 5597, 6686};
__constant__ int   c_size[5]  = {48, 43, 38, 33, 28};
__constant__ float c_scale[5] = {1.0f, 0.9f, 0.8f, 0.7f, 0.6f};

// Scratch (static device globals; no allocation)
__device__ float g_mb  [(size_t)BB * C2C * HWN];
__device__ float g_ref [(size_t)BB * CC  * LT];
__device__ float g_fm  [(size_t)BB * C2C * LT];
__device__ float g_fa  [(size_t)BB * CC  * LPD];   // stride LPD (16B-aligned rows)
__device__ float g_E   [(size_t)BB * LT];
__device__ int   g_meta[LT];
__device__ float2 g_mi [(size_t)BB * LT];          // (bitcast meta, 10/max(norm,esc))
__device__ float g_D   [(size_t)BB * HWN * LPD];   // D = mb^T * fm
__device__ float g_A   [(size_t)BB * HWN * LPD];   // attention weights
__device__ float g_part[(size_t)BB * NKC * HWN * CC]; // split-K partials

__device__ __forceinline__ float prelu(float v, float a) {
    return v >= 0.f ? v : a * v;
}

// FMA-pipe exp (valid for x <= 0): 2^z split + degree-7 poly, rel err ~5e-9.
__device__ __forceinline__ float fexp(float x) {
    float z = x * 1.4426950408889634f;
    z = fmaxf(z, -126.f);
    float r = rintf(z);
    float f = z - r;
    float p =           1.52527338e-5f;
    p = fmaf(p, f, 1.54035304e-4f);
    p = fmaf(p, f, 1.33335581e-3f);
    p = fmaf(p, f, 9.61812911e-3f);
    p = fmaf(p, f, 5.55041087e-2f);
    p = fmaf(p, f, 2.40226507e-1f);
    p = fmaf(p, f, 6.93147181e-1f);
    p = fmaf(p, f, 1.0f);
    int i = (int)r;
    return __int_as_float(__float_as_int(p) + (i << 23));
}

__device__ __forceinline__ float cubicw(float x) {   // torch bicubic, A=-0.75
    x = fabsf(x);
    if (x <= 1.f)  return (1.25f * x - 2.25f) * x * x + 1.f;
    if (x <  2.f)  return ((-0.75f * x + 3.75f) * x - 6.f) * x + 3.f;
    return 0.f;
}

__device__ __forceinline__ int find_scale(int l) {
    if (l < c_off[1]) return 0;
    if (l < c_off[2]) return 1;
    if (l < c_off[3]) return 2;
    if (l < c_off[4]) return 3;
    return 4;
}

__device__ __forceinline__ float warp_sum(float v) {
    #pragma unroll
    for (int o = 16; o > 0; o >>= 1) v += __shfl_down_sync(0xffffffffu, v, o);
    return v;
}
__device__ __forceinline__ float warp_max(float v) {
    #pragma unroll
    for (int o = 16; o > 0; o >>= 1) v = fmaxf(v, __shfl_down_sync(0xffffffffu, v, o));
    return v;
}

// ---------------------------------------------------------------------------
// 0. Per-l metadata: scale width n + scale-grid boundary validity bits
// ---------------------------------------------------------------------------
__global__ void k_meta() {
    int l = blockIdx.x * 256 + threadIdx.x;
    if (l >= LT) return;
    int s  = find_scale(l);
    int ll = l - c_off[s];
    int n  = c_size[s];
    int hl = ll / n, wl = ll - hl * n;
    int m = n;
    if (hl > 0)     m |= 1 << 8;
    if (hl < n - 1) m |= 1 << 9;
    if (wl > 0)     m |= 1 << 10;
    if (wl < n - 1) m |= 1 << 11;
    g_meta[l] = m;
}

// ---------------------------------------------------------------------------
// 1. match_base = prelu(w_mb @ x + b_mb) -> [B, 32, 2304]
// ---------------------------------------------------------------------------
__global__ void k_mb(const float* __restrict__ x, const float* __restrict__ w,
                     const float* __restrict__ b, const float* __restrict__ a) {
    int idx = blockIdx.x * blockDim.x + threadIdx.x;
    if (idx >= BB * C2C * HWN) return;
    int p  = idx % HWN;
    int t  = idx / HWN;
    int c2 = t % C2C;
    int bb = t / C2C;
    const float* xb = x + (size_t)bb * CC * HWN;
    float s = b[c2];
    #pragma unroll 8
    for (int c = 0; c < CC; c++) s = fmaf(w[c2 * CC + c], xb[(size_t)c * HWN + p], s);
    g_mb[idx] = prelu(s, a[0]);
}

// ---------------------------------------------------------------------------
// 2. Pyramid ref images (bicubic downsample; scale 0 = identity copy)
// ---------------------------------------------------------------------------
__global__ void k_ref(const float* __restrict__ x) {
    int idx = blockIdx.x * blockDim.x + threadIdx.x;
    if (idx >= BB * CC * LT) return;
    int l  = idx % LT;
    int t  = idx / LT;
    int c  = t % CC;
    int bb = t / CC;
    int s  = find_scale(l);
    int ll = l - c_off[s];
    const float* xb = x + ((size_t)bb * CC + c) * HWN;
    float out;
    if (s == 0) {
        out = xb[ll];
    } else {
        int n  = c_size[s];
        int oh = ll / n, ow = ll % n;
        float sc   = c_scale[s];
        float srcy = (oh + 0.5f) / sc - 0.5f;
        float srcx = (ow + 0.5f) / sc - 0.5f;
        int   fy = (int)floorf(srcy);
        int   fx = (int)floorf(srcx);
        float fry = srcy - fy, frx = srcx - fx;
        float wy[4], wx[4];
        #pragma unroll
        for (int k = 0; k < 4; k++) {
            wy[k] = cubicw((float)(k - 1) - fry);
            wx[k] = cubicw((float)(k - 1) - frx);
        }
        out = 0.f;
        #pragma unroll
        for (int ky = 0; ky < 4; ky++) {
            int iy = min(max(fy + ky - 1, 0), HH - 1);
            float acc = 0.f;
            #pragma unroll
            for (int kx = 0; kx < 4; kx++) {
                int ix = min(max(fx + kx - 1, 0), WWD - 1);
                acc = fmaf(wx[kx], xb[iy * WWD + ix], acc);
            }
            out = fmaf(wy[ky], acc, out);
        }
    }
    g_ref[idx] = out;
}

// ---------------------------------------------------------------------------
// 3. Both 1x1 convs over the pyramid in one pass (smem-tiled)
// ---------------------------------------------------------------------------
#define CT 64
__global__ void k_convs(const float* __restrict__ w_m, const float* __restrict__ b_m,
                        const float* __restrict__ a_m,
                        const float* __restrict__ w_a, const float* __restrict__ b_a,
                        const float* __restrict__ a_a) {
    __shared__ float sRef[CC][CT];
    __shared__ float sW[96][CC];
    int bb = blockIdx.y;
    int l0 = blockIdx.x * CT;
    int tid = threadIdx.x;
    for (int e = tid; e < 96 * CC; e += 256) {
        int co = e / CC, c = e % CC;
        sW[co][c] = (co < C2C) ? w_m[co * CC + c] : w_a[(co - C2C) * CC + c];
    }
    for (int e = tid; e < CC * CT; e += 256) {
        int c = e / CT, j = e % CT;
        sRef[c][j] = (l0 + j < LT) ? g_ref[((size_t)bb * CC + c) * LT + l0 + j] : 0.f;
    }
    __syncthreads();
    float am = a_m[0], aa = a_a[0];
    for (int o = tid; o < 96 * CT; o += 256) {
        int co = o / CT, j = o % CT;
        if (l0 + j >= LT) continue;
        float s = (co < C2C) ? b_m[co] : b_a[co - C2C];
        #pragma unroll 16
        for (int c = 0; c < CC; c++) s = fmaf(sW[co][c], sRef[c][j], s);
        if (co < C2C)
            g_fm[((size_t)bb * C2C + co) * LT + l0 + j] = prelu(s, am);
        else
            g_fa[((size_t)bb * CC + (co - C2C)) * LPD + l0 + j] = prelu(s, aa);
    }
}

// ---------------------------------------------------------------------------
// 4a. E[b,l] = sum_c2 fm^2
// ---------------------------------------------------------------------------
__global__ void k_E() {
    int idx = blockIdx.x * 256 + threadIdx.x;
    if (idx >= BB * LT) return;
    int l = idx % LT, bb = idx / LT;
    float s = 0.f;
    #pragma unroll 8
    for (int c2 = 0; c2 < C2C; c2++) {
        float v = g_fm[((size_t)bb * C2C + c2) * LT + l];
        s = fmaf(v, v, s);
    }
    g_E[idx] = s;
}

// ---------------------------------------------------------------------------
// 4b. mi[b,l] = (meta bits, 10 / max(sqrt(blur9(E)), esc))
// ---------------------------------------------------------------------------
__global__ void k_mi(const float* __restrict__ esc) {
    int idx = blockIdx.x * 256 + threadIdx.x;
    if (idx >= BB * LT) return;
    int l = idx % LT, bb = idx / LT;
    int m = g_meta[l];
    int n = m & 255;
    int my0 = (m >> 8) & 1, my2 = (m >> 9) & 1;
    int mx0 = (m >> 10) & 1, mx2 = (m >> 11) & 1;
    const float* E = g_E + (size_t)bb * LT;
    float s = 0.f;
    #pragma unroll
    for (int dy = 0; dy < 3; dy++) {
        int yok = (dy == 0) ? my0 : (dy == 2) ? my2 : 1;
        if (!yok) continue;
        #pragma unroll
        for (int dx = 0; dx < 3; dx++) {
            int xok = (dx == 0) ? mx0 : (dx == 2) ? mx2 : 1;
            if (!xok) continue;
            s += E[l + (dy - 1) * n + (dx - 1)];
        }
    }
    float inv = 10.f / fmaxf(sqrtf(s), esc[0]);
    g_mi[idx] = make_float2(__int_as_float(m), inv);
}

// ---------------------------------------------------------------------------
// 5. D = mb^T * fm : [2304, LPD], K=32  (pad cols -> 0), float4 fragments
// ---------------------------------------------------------------------------
__global__ void __launch_bounds__(256) k_D() {
    int bb = blockIdx.z;
    int m0 = blockIdx.y * 64, n0 = blockIdx.x * 64;
    __shared__ __align__(16) float As[C2C][68];
    __shared__ __align__(16) float Bs[C2C][68];
    int tid = threadIdx.y * 16 + threadIdx.x;
    #pragma unroll
    for (int t = 0; t < 8; t++) {
        int e = tid + t * 256;
        int k = e >> 6, col = e & 63;
        As[k][col] = g_mb[((size_t)bb * C2C + k) * HWN + m0 + col];
        Bs[k][col] = (n0 + col < LT) ? g_fm[((size_t)bb * C2C + k) * LT + n0 + col] : 0.f;
    }
    __syncthreads();
    float acc[4][4] = {};
    #pragma unroll
    for (int kk = 0; kk < C2C; kk++) {
        float4 a4 = *(const float4*)&As[kk][threadIdx.y * 4];
        float4 b4 = *(const float4*)&Bs[kk][threadIdx.x * 4];
        float av[4] = {a4.x, a4.y, a4.z, a4.w};
        float bv[4] = {b4.x, b4.y, b4.z, b4.w};
        #pragma unroll
        for (int i = 0; i < 4; i++)
            #pragma unroll
            for (int j = 0; j < 4; j++) acc[i][j] = fmaf(av[i], bv[j], acc[i][j]);
    }
    float* Dp = g_D + (size_t)bb * HWN * LPD;
    #pragma unroll
    for (int i = 0; i < 4; i++) {
        float4 v = make_float4(acc[i][0], acc[i][1], acc[i][2], acc[i][3]);
        *(float4*)&Dp[(size_t)(m0 + threadIdx.y * 4 + i) * LPD + n0 + threadIdx.x * 4] = v;
    }
}

// ---------------------------------------------------------------------------
// 6. Fused softmax: S = inv[l]*blur9(D) -> softmax -> A row (fp32).
//    1 block (512 thr) per (b,p); packed meta+inv table; float4 passes 2/3.
// ---------------------------------------------------------------------------
#define LT4 7472    // LT rounded up to multiple of 4
__global__ void __launch_bounds__(512) k_sm() {
    int bp = blockIdx.x;
    int p  = bp % HWN;
    int bb = bp / HWN;
    int h = p / WWD, w = p % WWD;
    int hy0 = (h > 0), hy2 = (h < HH - 1);
    int wx0 = (w > 0), wx2 = (w < WWD - 1);
    const float* D = g_D + (size_t)bb * HWN * LPD + (size_t)p * LPD;
    float* A = g_A + (size_t)bb * HWN * LPD + (size_t)p * LPD;
    const float2* mi = g_mi + (size_t)bb * LT;

    __shared__ __align__(16) float buf[LT4];
    __shared__ float red[16];
    int tid = threadIdx.x;
    float mx = -1e30f;
    for (int l = tid; l < LT; l += 512) {
        float2 mv = mi[l];
        int m = __float_as_int(mv.x);
        int n = m & 255;
        float acc = 0.f;
        #pragma unroll
        for (int dy = 0; dy < 3; dy++) {
            int yok = (dy == 0) ? (hy0 & ((m >> 8) & 1))
                    : (dy == 2) ? (hy2 & ((m >> 9) & 1)) : 1;
            if (!yok) continue;
            const float* Drow = D + (dy - 1) * WWD * LPD + (dy - 1) * n;
            #pragma unroll
            for (int dx = 0; dx < 3; dx++) {
                int xok = (dx == 0) ? (wx0 & ((m >> 10) & 1))
                        : (dx == 2) ? (wx2 & ((m >> 11) & 1)) : 1;
                if (!xok) continue;
                acc += Drow[(dx - 1) * LPD + l + (dx - 1)];
            }
        }
        float v = acc * mv.y;
        buf[l] = v;
        mx = fmaxf(mx, v);
    }
    if (tid < LT4 - LT) buf[LT + tid] = -1e30f;   // sentinel pad (exp -> ~0)
    mx = warp_max(mx);
    if ((tid & 31) == 0) red[tid >> 5] = mx;
    __syncthreads();
    if (tid < 16) {
        float v = red[tid];
        #pragma unroll
        for (int o = 8; o > 0; o >>= 1) v = fmaxf(v, __shfl_down_sync(0xffffu, v, o));
        if (tid == 0) red[0] = v;
    }
    __syncthreads();
    mx = red[0];
    __syncthreads();
    float sum = 0.f;
    for (int l4 = tid * 4; l4 < LT4; l4 += 2048) {
        float4 v = *(float4*)&buf[l4];
        v.x = fexp(v.x - mx);
        v.y = fexp(v.y - mx);
        v.z = fexp(v.z - mx);
        v.w = fexp(v.w - mx);
        *(float4*)&buf[l4] = v;
        sum += (v.x + v.y) + (v.z + v.w);
    }
    sum = warp_sum(sum);
    if ((tid & 31) == 0) red[tid >> 5] = sum;
    __syncthreads();
    if (tid < 16) {
        float v = red[tid];
        #pragma unroll
        for (int o = 8; o > 0; o >>= 1) v += __shfl_down_sync(0xffffu, v, o);
        if (tid == 0) red[0] = v;
    }
    __syncthreads();
    float is = 1.f / red[0];
    for (int l4 = tid * 4; l4 < LT4; l4 += 2048) {
        float4 v = *(float4*)&buf[l4];
        v.x *= is; v.y *= is; v.z *= is; v.w *= is;
        *(float4*)&A[l4] = v;
    }
}

// ---------------------------------------------------------------------------
// 7. Split-K partial GEMM with fused blur9(A) tile build (R12 geometry):
//    grid (72 m-tiles, 13 k-chunks, B); block (16,8)=128; 32x64 tile, TK=24
//    4x4 microtile (float4 fragments both sides).
// ---------------------------------------------------------------------------
#define TK2 24
__global__ void __launch_bounds__(128) k_gemm2p() {
    int bb = blockIdx.z;
    int kc = blockIdx.y;
    int m0 = blockIdx.x * 32;
    __shared__ __align__(16) float As[TK2][36];   // [k][m] blurred attention
    __shared__ __align__(16) float Bs[TK2][68];   // [k][c] fa
    int tid = threadIdx.y * 16 + threadIdx.x;     // 0..127
    const float* Ab = g_A + (size_t)bb * HWN * LPD;
    const float* fa = g_fa + (size_t)bb * CC * LPD;
    float acc[4][4] = {};
    int kend = kc * KCH + KCH;
    for (int k0 = kc * KCH; k0 < kend; k0 += TK2) {
        // ---- blurred A tile: 32 rows (p) x 24 cols (l); 6 elems/thread ----
        #pragma unroll
        for (int t = 0; t < 6; t++) {
            int e = tid + t * 128;
            int r = e / TK2, kk = e % TK2;
            int l = k0 + kk;
            float v = 0.f;
            if (l < LT) {
                int p = m0 + r;
                int h = p / WWD, w = p % WWD;
                int hy0 = (h > 0), hy2 = (h < HH - 1);
                int wx0 = (w > 0), wx2 = (w < WWD - 1);
                int m = g_meta[l];
                int n = m & 255;
                const float* Arow = Ab + (size_t)p * LPD + l;
                #pragma unroll
                for (int dy = 0; dy < 3; dy++) {
                    int yok = (dy == 0) ? (hy0 & ((m >> 8) & 1))
                            : (dy == 2) ? (hy2 & ((m >> 9) & 1)) : 1;
                    if (!yok) continue;
                    const float* Ar2 = Arow + (dy - 1) * (WWD * LPD) + (dy - 1) * n;
                    #pragma unroll
                    for (int dx = 0; dx < 3; dx++) {
                        int xok = (dx == 0) ? (wx0 & ((m >> 10) & 1))
                                : (dx == 2) ? (wx2 & ((m >> 11) & 1)) : 1;
                        if (!xok) continue;
                        v += Ar2[(dx - 1) * LPD + (dx - 1)];
                    }
                }
            }
            As[kk][r] = v;
        }
        // ---- fa tile: 64 c x 24 k; float4 loads, 384 total (3/thread) ----
        #pragma unroll
        for (int t = 0; t < 3; t++) {
            int e = tid + t * 128;          // [0, 384)
            int c = e / 6;                  // 0..63
            int q = e % 6;                  // 0..5 (quad within 24 k)
            int l = k0 + q * 4;
            float4 v = *(const float4*)&fa[(size_t)c * LPD + l];
            Bs[q * 4 + 0][c] = (l + 0 < LT) ? v.x : 0.f;
            Bs[q * 4 + 1][c] = (l + 1 < LT) ? v.y : 0.f;
            Bs[q * 4 + 2][c] = (l + 2 < LT) ? v.z : 0.f;
            Bs[q * 4 + 3][c] = (l + 3 < LT) ? v.w : 0.f;
        }
        __syncthreads();
        #pragma unroll
        for (int kk = 0; kk < TK2; kk++) {
            float4 a4 = *(const float4*)&As[kk][threadIdx.y * 4];
            float4 b4 = *(const float4*)&Bs[kk][threadIdx.x * 4];
            float av[4] = {a4.x, a4.y, a4.z, a4.w};
            float bv[4] = {b4.x, b4.y, b4.z, b4.w};
            #pragma unroll
            for (int i = 0; i < 4; i++)
                #pragma unroll
                for (int j = 0; j < 4; j++) acc[i][j] = fmaf(av[i], bv[j], acc[i][j]);
        }
        __syncthreads();
    }
    #pragma unroll
    for (int i = 0; i < 4; i++) {
        int p = m0 + threadIdx.y * 4 + i;
        float4 v = make_float4(acc[i][0], acc[i][1], acc[i][2], acc[i][3]);
        *(float4*)&g_part[(((size_t)bb * NKC + kc) * HWN + p) * CC + threadIdx.x * 4] = v;
    }
}

// ---------------------------------------------------------------------------
// 8. Reduce split-K partials + residual (float4 over c)
// ---------------------------------------------------------------------------
__global__ void k_out(const float* __restrict__ x, float* __restrict__ out) {
    int idx = blockIdx.x * 256 + threadIdx.x;          // (b,p,c4)
    if (idx >= BB * HWN * (CC / 4)) return;
    int c4 = idx % (CC / 4);
    int t  = idx / (CC / 4);
    int p  = t % HWN;
    int bb = t / HWN;
    float4 s = make_float4(0.f, 0.f, 0.f, 0.f);
    #pragma unroll
    for (int kc = 0; kc < NKC; kc++) {
        float4 v = *(const float4*)&g_part[(((size_t)bb * NKC + kc) * HWN + p) * CC + c4 * 4];
        s.x += v.x; s.y += v.y; s.z += v.z; s.w += v.w;
    }
    int c = c4 * 4;
    size_t o0 = ((size_t)bb * CC + c) * HWN + p;
    out[o0]           = x[o0]           + 0.25f * s.x;
    out[o0 + HWN]     = x[o0 + HWN]     + 0.25f * s.y;
    out[o0 + 2 * HWN] = x[o0 + 2 * HWN] + 0.25f * s.z;
    out[o0 + 3 * HWN] = x[o0 + 3 * HWN] + 0.25f * s.w;
}

// ---------------------------------------------------------------------------
extern "C" void kernel_launch(void* const* d_in, const int* in_sizes, int n_in,
                              void* d_out, int out_size) {
    const float* x    = (const float*)d_in[0];
    const float* w_mb = (const float*)d_in[1];
    const float* b_mb = (const float*)d_in[2];
    const float* a_mb = (const float*)d_in[3];
    const float* w_m  = (const float*)d_in[4];
    const float* b_m  = (const float*)d_in[5];
    const float* a_m  = (const float*)d_in[6];
    const float* w_a  = (const float*)d_in[7];
    const float* b_a  = (const float*)d_in[8];
    const float* a_a  = (const float*)d_in[9];
    const float* esc  = (const float*)d_in[10];
    float* out = (float*)d_out;

    k_meta<<<(LT + 255) / 256, 256>>>();

    int n = BB * C2C * HWN;
    k_mb<<<(n + 255) / 256, 256>>>(x, w_mb, b_mb, a_mb);

    n = BB * CC * LT;
    k_ref<<<(n + 255) / 256, 256>>>(x);

    {
        dim3 grid((LT + CT - 1) / CT, BB);
        k_convs<<<grid, 256>>>(w_m, b_m, a_m, w_a, b_a, a_a);
    }

    n = BB * LT;
    k_E<<<(n + 255) / 256, 256>>>();
    k_mi<<<(n + 255) / 256, 256>>>(esc);

    {
        dim3 grid(LPD / 64, HWN / 64, BB), block(16, 16);
        k_D<<<grid, block>>>();
    }

    k_sm<<<BB * HWN, 512>>>();

    {
        dim3 grid(HWN / 32, NKC, BB), block(16, 8);
        k_gemm2p<<<grid, block>>>();
    }

    n = BB * HWN * (CC / 4);
    k_out<<<(n + 255) / 256, 256>>>(x, out);
}